// round 16
// baseline (speedup 1.0000x reference)
#include <cuda_runtime.h>
#include <cuda_fp16.h>
#include <cstdint>

#define BATCH 2
#define CIN   192
#define IMG   56
#define HWSZ  3136
#define ODIM  192
#define HEADS 6
#define DH    32
#define TW    8
#define TH    8
#define HLW   14
#define HLH   14
#define HPX   196

// -------- scratch (static device globals; no allocation) --------
__device__ __align__(128) __half g_xt_hi[(size_t)BATCH * HWSZ * CIN];   // x^T hi [b][p][c]
__device__ __align__(128) __half g_xt_lo[(size_t)BATCH * HWSZ * CIN];
__device__ __align__(128) __half g_w[4u * ODIM * CIN];                  // wq,wk,wv,wproj fp16
__device__ __align__(128) float  g_qkv[(size_t)BATCH * HWSZ * 3 * ODIM];// [b][p][{q|k|v}192]
__device__ __align__(128) __half g_ah[(size_t)BATCH * HWSZ * ODIM];     // attn out fp16 [b][p][c]

__device__ __forceinline__ uint32_t smem_u32(const void* p) {
    uint32_t a;
    asm("{ .reg .u64 t; cvta.to.shared.u64 t, %1; cvt.u32.u64 %0, t; }" : "=r"(a) : "l"(p));
    return a;
}
__device__ __forceinline__ void ldsm4(uint32_t* r, uint32_t addr) {
    asm volatile("ldmatrix.sync.aligned.m8n8.x4.shared.b16 {%0,%1,%2,%3}, [%4];"
        : "=r"(r[0]), "=r"(r[1]), "=r"(r[2]), "=r"(r[3]) : "r"(addr));
}
__device__ __forceinline__ void mma16816(float* c, const uint32_t* a, const uint32_t* b) {
    asm volatile("mma.sync.aligned.m16n8k16.row.col.f32.f16.f16.f32 "
        "{%0,%1,%2,%3}, {%4,%5,%6,%7}, {%8,%9}, {%0,%1,%2,%3};"
        : "+f"(c[0]), "+f"(c[1]), "+f"(c[2]), "+f"(c[3])
        : "r"(a[0]), "r"(a[1]), "r"(a[2]), "r"(a[3]), "r"(b[0]), "r"(b[1]));
}
__device__ __forceinline__ uint32_t swz(uint32_t off) { return off ^ ((off >> 3) & 0x70); }
__device__ __forceinline__ void cpasync16(uint32_t dst, const void* src) {
    asm volatile("cp.async.cg.shared.global [%0], [%1], 16;" :: "r"(dst), "l"(src));
}
#define CP_COMMIT() asm volatile("cp.async.commit_group;" ::: "memory")
#define CP_WAIT(n)  asm volatile("cp.async.wait_group %0;" :: "n"(n) : "memory")

// -------- fused prep: W fp16 (blocks 0..287) + x transpose hi/lo (rest) ------
__global__ __launch_bounds__(256) void prep_kernel(const float* __restrict__ wq, const float* __restrict__ wk,
                                                   const float* __restrict__ wv, const float* __restrict__ wp,
                                                   const float* __restrict__ x)
{
    const int bid = blockIdx.x;
    if (bid < 288) {
        int idx = bid * 256 + threadIdx.x;          // float2 index; 4*36864/2 total
        if (idx >= 73728) return;
        int mat = idx / 18432, off = idx - mat * 18432;
        const float* src = (mat == 0) ? wq : (mat == 1) ? wk : (mat == 2) ? wv : wp;
        float2 w = ((const float2*)src)[off];
        ((__half2*)g_w)[idx] = __floats2half2_rn(w.x, w.y);
        return;
    }
    __shared__ float sm[32][33];
    const int e = bid - 288;                        // 98*6*2 tiles
    const int p0 = (e % 98) * 32, c0 = ((e / 98) % 6) * 32, b = e / 588;
    const int tx = threadIdx.x & 31, ty = threadIdx.x >> 5;
    #pragma unroll
    for (int j = 0; j < 4; j++)
        sm[ty + 8 * j][tx] = x[((size_t)b * CIN + c0 + ty + 8 * j) * HWSZ + p0 + tx];
    __syncthreads();
    #pragma unroll
    for (int j = 0; j < 4; j++) {
        int p = p0 + ty + 8 * j, c = c0 + tx;
        float v = sm[tx][ty + 8 * j];
        __half h = __float2half_rn(v);
        __half l = __float2half_rn(v - __half2float(h));
        g_xt_hi[((size_t)b * HWSZ + p) * CIN + c] = h;
        g_xt_lo[((size_t)b * HWSZ + p) * CIN + c] = l;
    }
}

// -------- GEMM building blocks (128 threads / 4 warps, 64x64 tile) ----------
#define GTHREADS 128
#define QKV_SMEM  57344   // B resident 24K + A dbuf 2x16K
#define PROJ_SMEM 32768   // 2 x (A 8K + B 8K)

// A chunk (hi+lo) -> sbuf: Ah [0,8K), Al [8K,16K). Rows clamped to HWSZ-1.
__device__ __forceinline__ void stage_a2(const __half* __restrict__ Ah, const __half* __restrict__ Al,
                                         int p0, int c0, uint32_t sbuf)
{
    const int tid = threadIdx.x;
    #pragma unroll
    for (int it = 0; it < 4; it++) {
        int i = tid + it * GTHREADS;            // 512: 64 rows x 8 octs
        int r = i >> 3, oct = i & 7;
        int pp = p0 + r; if (pp > HWSZ - 1) pp = HWSZ - 1;
        uint32_t db = swz((uint32_t)(r * 128 + oct * 16));
        const size_t aoff = (size_t)pp * CIN + c0 + oct * 8;
        cpasync16(sbuf + db,        Ah + aoff);
        cpasync16(sbuf + 8192 + db, Al + aoff);
    }
}

// A chunk (hi only) + B chunk -> sbuf: A [0,8K), B [8K,16K)
__device__ __forceinline__ void stage_a1b(const __half* __restrict__ Ah, const __half* __restrict__ B,
                                          int p0, int c0, uint32_t sbuf)
{
    const int tid = threadIdx.x;
    #pragma unroll
    for (int it = 0; it < 4; it++) {
        int i = tid + it * GTHREADS;            // 512: 64 rows x 8 octs
        int r = i >> 3, oct = i & 7;
        uint32_t db = swz((uint32_t)(r * 128 + oct * 16));
        cpasync16(sbuf + db,        Ah + (size_t)(p0 + r) * CIN + c0 + oct * 8);
        cpasync16(sbuf + 8192 + db, B + (size_t)r * CIN + c0 + oct * 8);
    }
}

// full-K B (64 rows x 192) -> sbase: 3 chunks of 8K, chunk-major
__device__ __forceinline__ void stage_b_full(const __half* __restrict__ B, uint32_t sbase)
{
    const int tid = threadIdx.x;
    #pragma unroll
    for (int it = 0; it < 12; it++) {
        int i = tid + it * GTHREADS;            // 1536: 3 chunks x 64 rows x 8 octs
        int ch = i >> 9, r = (i & 511) >> 3, oct = i & 7;
        uint32_t db = swz((uint32_t)(r * 128 + oct * 16)) + ch * 8192;
        cpasync16(sbase + db, B + (size_t)r * CIN + ch * 64 + oct * 8);
    }
}

template<bool TWOPASS>
__device__ __forceinline__ void compute_chunk(uint32_t abuf, uint32_t bbase, float acc[2][4][4])
{
    const int lane = threadIdx.x & 31, wid = threadIdx.x >> 5;
    const int wm = wid & 1, wn = wid >> 1;      // warp tile: rows wm*32, cols wn*32
    const int a_row_l = lane & 15, a_k_l = lane >> 4;
    const int b_row_l = (lane & 7) + ((lane >> 4) << 3), b_k_l = (lane >> 3) & 1;

    #pragma unroll
    for (int ks = 0; ks < 4; ks++) {
        uint32_t ah[2][4], al[2][4], b[2][4];
        #pragma unroll
        for (int np = 0; np < 2; np++) {
            int row = wn * 32 + np * 16 + b_row_l;
            int c16 = ks * 2 + b_k_l;
            ldsm4(b[np], bbase + swz((uint32_t)(row * 128 + c16 * 16)));
        }
        #pragma unroll
        for (int mi = 0; mi < 2; mi++) {
            int row = wm * 32 + mi * 16 + a_row_l;
            int c16 = ks * 2 + a_k_l;
            uint32_t off = swz((uint32_t)(row * 128 + c16 * 16));
            ldsm4(ah[mi], abuf + off);
            if (TWOPASS) ldsm4(al[mi], abuf + 8192 + off);
        }
        #pragma unroll
        for (int mi = 0; mi < 2; mi++)
            #pragma unroll
            for (int ni = 0; ni < 4; ni++) {
                mma16816(acc[mi][ni], ah[mi], &b[ni >> 1][(ni & 1) * 2]);
                if (TWOPASS) mma16816(acc[mi][ni], al[mi], &b[ni >> 1][(ni & 1) * 2]);
            }
    }
}

// QKV: grid (25, 9, 2) = 450 blocks ~ 1 wave at 3 CTAs/SM. 2 p-tiles per block,
// weight strip (64x192) staged once and kept resident.
__global__ __launch_bounds__(GTHREADS, 3) void qkv_mma()
{
    extern __shared__ __align__(1024) char smem[];
    const uint32_t sbase = smem_u32(smem);
    const uint32_t BUF0 = sbase + 24576, BUF1 = sbase + 40960;
    const int p0 = blockIdx.x * 128, n0 = blockIdx.y * 64, b = blockIdx.z;
    const __half* Ah = g_xt_hi + (size_t)b * HWSZ * CIN;
    const __half* Al = g_xt_lo + (size_t)b * HWSZ * CIN;
    const __half* B  = g_w + (size_t)n0 * CIN;

    float acc[2][2][4][4];
    #pragma unroll
    for (int t = 0; t < 2; t++)
        #pragma unroll
        for (int mi = 0; mi < 2; mi++)
            #pragma unroll
            for (int ni = 0; ni < 4; ni++)
                #pragma unroll
                for (int e = 0; e < 4; e++) acc[t][mi][ni][e] = 0.f;

    stage_b_full(B, sbase);
    stage_a2(Ah, Al, p0, 0, BUF0);        CP_COMMIT();   // g0: B + A(t0,c0)
    stage_a2(Ah, Al, p0, 64, BUF1);       CP_COMMIT();   // g1: A(t0,c1)

    CP_WAIT(1); __syncthreads();
    compute_chunk<true>(BUF0, sbase, acc[0]);                      // t0,c0
    __syncthreads();
    stage_a2(Ah, Al, p0, 128, BUF0);      CP_COMMIT();   // A(t0,c2)
    CP_WAIT(1); __syncthreads();
    compute_chunk<true>(BUF1, sbase + 8192, acc[0]);               // t0,c1
    __syncthreads();
    stage_a2(Ah, Al, p0 + 64, 0, BUF1);   CP_COMMIT();   // A(t1,c0)
    CP_WAIT(1); __syncthreads();
    compute_chunk<true>(BUF0, sbase + 16384, acc[0]);              // t0,c2
    __syncthreads();
    stage_a2(Ah, Al, p0 + 64, 64, BUF0);  CP_COMMIT();   // A(t1,c1)
    CP_WAIT(1); __syncthreads();
    compute_chunk<true>(BUF1, sbase, acc[1]);                      // t1,c0
    __syncthreads();
    stage_a2(Ah, Al, p0 + 64, 128, BUF1); CP_COMMIT();   // A(t1,c2)
    CP_WAIT(1); __syncthreads();
    compute_chunk<true>(BUF0, sbase + 8192, acc[1]);               // t1,c1
    CP_WAIT(0); __syncthreads();
    compute_chunk<true>(BUF1, sbase + 16384, acc[1]);              // t1,c2

    const int lane = threadIdx.x & 31, wid = threadIdx.x >> 5;
    const int wm = wid & 1, wn = wid >> 1;
    const int gid = lane >> 2, tq = lane & 3;
    float* outb = g_qkv + (size_t)b * HWSZ * 576;
    #pragma unroll
    for (int t = 0; t < 2; t++) {
        #pragma unroll
        for (int mi = 0; mi < 2; mi++) {
            const int p = p0 + t * 64 + wm * 32 + mi * 16 + gid;
            #pragma unroll
            for (int ni = 0; ni < 4; ni++) {
                int o = n0 + wn * 32 + ni * 8 + tq * 2;
                if (p < HWSZ)
                    *(float2*)&outb[(size_t)p * 576 + o] = make_float2(acc[t][mi][ni][0], acc[t][mi][ni][1]);
                if (p + 8 < HWSZ)
                    *(float2*)&outb[(size_t)(p + 8) * 576 + o] = make_float2(acc[t][mi][ni][2], acc[t][mi][ni][3]);
            }
        }
    }
}

// Projection: grid (49, 3, 2), single-pass fp16 A. Channel-major out via smem.
__global__ __launch_bounds__(GTHREADS, 3) void proj_mma(float* __restrict__ out)
{
    extern __shared__ __align__(1024) char smem[];
    const uint32_t sbase = smem_u32(smem);
    const int p0 = blockIdx.x * 64, n0 = blockIdx.y * 64, b = blockIdx.z;
    const __half* Ah = g_ah + (size_t)b * HWSZ * ODIM;
    const __half* B  = g_w + (size_t)(3 * ODIM + n0) * CIN;

    float acc[2][4][4];
    #pragma unroll
    for (int mi = 0; mi < 2; mi++)
        #pragma unroll
        for (int ni = 0; ni < 4; ni++)
            #pragma unroll
            for (int e = 0; e < 4; e++) acc[mi][ni][e] = 0.f;

    stage_a1b(Ah, B, p0, 0, sbase);            CP_COMMIT();
    stage_a1b(Ah, B, p0, 64, sbase + 16384);   CP_COMMIT();

    CP_WAIT(1); __syncthreads();
    compute_chunk<false>(sbase, sbase + 8192, acc);
    __syncthreads();
    stage_a1b(Ah, B, p0, 128, sbase);          CP_COMMIT();
    CP_WAIT(1); __syncthreads();
    compute_chunk<false>(sbase + 16384, sbase + 24576, acc);
    CP_WAIT(0); __syncthreads();
    compute_chunk<false>(sbase, sbase + 8192, acc);

    const int tid = threadIdx.x, lane = tid & 31, wid = tid >> 5;
    const int wm = wid & 1, wn = wid >> 1;
    const int gid = lane >> 2, tq = lane & 3;
    float* st = (float*)smem;          // [64 o][68 p] = 17408B, reuses buf0
    __syncthreads();
    #pragma unroll
    for (int mi = 0; mi < 2; mi++) {
        const int pl = wm * 32 + mi * 16 + gid;
        #pragma unroll
        for (int ni = 0; ni < 4; ni++) {
            int ol = wn * 32 + ni * 8 + tq * 2;
            st[ol * 68 + pl]           = acc[mi][ni][0];
            st[(ol + 1) * 68 + pl]     = acc[mi][ni][1];
            st[ol * 68 + pl + 8]       = acc[mi][ni][2];
            st[(ol + 1) * 68 + pl + 8] = acc[mi][ni][3];
        }
    }
    __syncthreads();
    float* ob = out + (size_t)b * ODIM * HWSZ;
    #pragma unroll
    for (int it = 0; it < 8; it++) {
        int i = tid + it * GTHREADS;           // 1024: 64 o x 16 quads
        int o = i >> 4, pq = i & 15;
        float4 v = *(const float4*)&st[o * 68 + pq * 4];
        *(float4*)&ob[(size_t)(n0 + o) * HWSZ + p0 + pq * 4] = v;
    }
}

// -------- attention: 8x8 tile, 4 threads/pixel, 4 CTAs/SM -------------------
__global__ __launch_bounds__(256, 4) void attn_kernel(const float* __restrict__ pos)
{
    extern __shared__ __align__(16) float sm2[];
    float* ks = sm2;
    float* vs = sm2 + HPX * 32;
    __shared__ float sbias[13];

    const int tid = threadIdx.x;
    const int x0 = blockIdx.x * TW, y0 = blockIdx.y * TH;
    const int b = blockIdx.z / HEADS, h = blockIdx.z % HEADS;
    if (tid < 13) sbias[tid] = pos[tid];

    const float* base = g_qkv + (size_t)b * HWSZ * 576;
    const int hoff = h * DH;

    for (int idx = tid; idx < HPX * 8; idx += 256) {
        int pix = idx >> 3, g = idx & 7;
        int hy = pix / HLW, hx = pix - hy * HLW;
        int gy = y0 - 3 + hy, gx = x0 - 3 + hx;
        float4 kv = make_float4(0.f, 0.f, 0.f, 0.f);
        float4 vv = make_float4(0.f, 0.f, 0.f, 0.f);
        if (gy >= 0 && gy < IMG && gx >= 0 && gx < IMG) {
            const float* row = base + (size_t)(gy * IMG + gx) * 576 + hoff;
            kv = *(const float4*)(row + 192 + g * 4);
            vv = *(const float4*)(row + 384 + g * 4);
        }
        int slot = g ^ (pix & 7);
        *(float4*)&ks[pix * 32 + slot * 4] = kv;
        *(float4*)&vs[pix * 32 + slot * 4] = vv;
    }
    __syncthreads();

    const int pixel = tid >> 2, qt = tid & 3, lane = tid & 31;
    const int px = pixel & 7, py = pixel >> 3;
    const int gx = x0 + px, gy = y0 + py;
    const float* qrow = base + (size_t)(gy * IMG + gx) * 576 + hoff;

    const int nown = (qt == 0) ? 13 : 12;

    float lg[13];
    #pragma unroll
    for (int j = 0; j < 13; j++) lg[j] = 0.f;
    #pragma unroll
    for (int hf = 0; hf < 4; hf++) {
        float qr[8];
        #pragma unroll
        for (int g = 0; g < 2; g++) {
            float4 q4 = *(const float4*)(qrow + hf * 8 + g * 4);
            qr[4 * g + 0] = q4.x; qr[4 * g + 1] = q4.y; qr[4 * g + 2] = q4.z; qr[4 * g + 3] = q4.w;
        }
        #pragma unroll
        for (int j = 0; j < 13; j++) {
            if (j < nown) {
                const int kk = 4 * j + qt;
                const int di = kk / 7, dj = kk % 7;
                const int hp = (py + di) * HLW + (px + dj);
                const float* kb = &ks[hp * 32];
                const int sw = hp & 7;
                float s0 = 0.f, s1 = 0.f;
                #pragma unroll
                for (int g = 0; g < 2; g++) {
                    const int d4 = hf * 2 + g;
                    float4 kv = *(const float4*)&kb[((d4 ^ sw) << 2)];
                    s0 += kv.x * qr[4 * g + 0] + kv.z * qr[4 * g + 2];
                    s1 += kv.y * qr[4 * g + 1] + kv.w * qr[4 * g + 3];
                }
                lg[j] += s0 + s1;
            }
        }
    }
    #pragma unroll
    for (int j = 0; j < 13; j++) {
        if (j < nown) {
            const int kk = 4 * j + qt;
            lg[j] += sbias[kk / 7 + kk % 7];
        } else lg[j] = -1e30f;
    }

    float mx = -1e30f;
    #pragma unroll
    for (int j = 0; j < 13; j++) mx = fmaxf(mx, lg[j]);
    mx = fmaxf(mx, __shfl_xor_sync(0xffffffffu, mx, 1));
    mx = fmaxf(mx, __shfl_xor_sync(0xffffffffu, mx, 2));
    float sum = 0.f;
    #pragma unroll
    for (int j = 0; j < 13; j++) if (j < nown) { lg[j] = __expf(lg[j] - mx); sum += lg[j]; }
    sum += __shfl_xor_sync(0xffffffffu, sum, 1);
    sum += __shfl_xor_sync(0xffffffffu, sum, 2);
    const float inv = 1.f / sum;
    #pragma unroll
    for (int j = 0; j < 13; j++) lg[j] *= inv;

    float ot[8];
    #pragma unroll
    for (int d = 0; d < 8; d++) ot[d] = 0.f;
    #pragma unroll
    for (int kk = 0; kk < 49; kk++) {
        const int di = kk / 7, dj = kk % 7;
        const int hp = (py + di) * HLW + (px + dj);
        const float* vb = &vs[hp * 32];
        const int sw = hp & 7;
        const float w = __shfl_sync(0xffffffffu, lg[kk >> 2], (lane & 0x1C) | (kk & 3));
        #pragma unroll
        for (int i = 0; i < 2; i++) {
            const int d4 = 2 * qt + i;
            float4 vv = *(const float4*)&vb[((d4 ^ sw) << 2)];
            ot[4 * i + 0] += w * vv.x;
            ot[4 * i + 1] += w * vv.y;
            ot[4 * i + 2] += w * vv.z;
            ot[4 * i + 3] += w * vv.w;
        }
    }

    const size_t orow = ((size_t)b * HWSZ + gy * IMG + gx) * ODIM + hoff + qt * 8;
    __half2* oh = (__half2*)(g_ah + orow);
    #pragma unroll
    for (int j = 0; j < 4; j++)
        oh[j] = __floats2half2_rn(ot[2 * j], ot[2 * j + 1]);
}

// ---------------------------------------------------------------------------
extern "C" void kernel_launch(void* const* d_in, const int* in_sizes, int n_in,
                              void* d_out, int out_size)
{
    const float* x   = (const float*)d_in[0];
    const float* wq  = (const float*)d_in[1];
    const float* wk  = (const float*)d_in[2];
    const float* wv  = (const float*)d_in[3];
    const float* pos = (const float*)d_in[4];
    const float* wp  = (const float*)d_in[5];
    float* out = (float*)d_out;

    const int attn_smem = 2 * HPX * 32 * (int)sizeof(float); // 50176
    cudaFuncSetAttribute(qkv_mma,  cudaFuncAttributeMaxDynamicSharedMemorySize, QKV_SMEM);
    cudaFuncSetAttribute(proj_mma, cudaFuncAttributeMaxDynamicSharedMemorySize, PROJ_SMEM);
    cudaFuncSetAttribute(attn_kernel, cudaFuncAttributeMaxDynamicSharedMemorySize, attn_smem);

    prep_kernel<<<288 + 1176, 256>>>(wq, wk, wv, wp, x);
    qkv_mma<<<dim3(25, 9, 2), GTHREADS, QKV_SMEM>>>();
    attn_kernel<<<dim3(7, 7, 12), 256, attn_smem>>>(pos);
    proj_mma<<<dim3(49, 3, 2), GTHREADS, PROJ_SMEM>>>(out);
}

// round 17
// speedup vs baseline: 1.0494x; 1.0494x over previous
#include <cuda_runtime.h>
#include <cuda_fp16.h>
#include <cstdint>

#define BATCH 2
#define CIN   192
#define IMG   56
#define HWSZ  3136
#define ODIM  192
#define HEADS 6
#define DH    32
#define TW    8
#define TH    8
#define HLW   14
#define HLH   14
#define HPX   196

// -------- scratch (static device globals; no allocation) --------
__device__ __align__(128) __half g_xt_hi[(size_t)BATCH * HWSZ * CIN];   // x^T hi [b][p][c]
__device__ __align__(128) __half g_xt_lo[(size_t)BATCH * HWSZ * CIN];
__device__ __align__(128) __half g_w[4u * ODIM * CIN];                  // wq,wk,wv,wproj fp16
__device__ __align__(128) float  g_qkv[(size_t)BATCH * HWSZ * 3 * ODIM];// [b][p][{q|k|v}192]
__device__ __align__(128) __half g_ah[(size_t)BATCH * HWSZ * ODIM];     // attn out fp16 [b][p][c]

__device__ __forceinline__ uint32_t smem_u32(const void* p) {
    uint32_t a;
    asm("{ .reg .u64 t; cvta.to.shared.u64 t, %1; cvt.u32.u64 %0, t; }" : "=r"(a) : "l"(p));
    return a;
}
__device__ __forceinline__ void ldsm4(uint32_t* r, uint32_t addr) {
    asm volatile("ldmatrix.sync.aligned.m8n8.x4.shared.b16 {%0,%1,%2,%3}, [%4];"
        : "=r"(r[0]), "=r"(r[1]), "=r"(r[2]), "=r"(r[3]) : "r"(addr));
}
__device__ __forceinline__ void mma16816(float* c, const uint32_t* a, const uint32_t* b) {
    asm volatile("mma.sync.aligned.m16n8k16.row.col.f32.f16.f16.f32 "
        "{%0,%1,%2,%3}, {%4,%5,%6,%7}, {%8,%9}, {%0,%1,%2,%3};"
        : "+f"(c[0]), "+f"(c[1]), "+f"(c[2]), "+f"(c[3])
        : "r"(a[0]), "r"(a[1]), "r"(a[2]), "r"(a[3]), "r"(b[0]), "r"(b[1]));
}
__device__ __forceinline__ uint32_t swz(uint32_t off) { return off ^ ((off >> 3) & 0x70); }
__device__ __forceinline__ void cpasync16(uint32_t dst, const void* src) {
    asm volatile("cp.async.cg.shared.global [%0], [%1], 16;" :: "r"(dst), "l"(src));
}
#define CP_COMMIT() asm volatile("cp.async.commit_group;" ::: "memory")
#define CP_WAIT(n)  asm volatile("cp.async.wait_group %0;" :: "n"(n) : "memory")

// -------- fused prep: W fp16 (blocks 0..287) + x transpose hi/lo (rest) ------
__global__ __launch_bounds__(256) void prep_kernel(const float* __restrict__ wq, const float* __restrict__ wk,
                                                   const float* __restrict__ wv, const float* __restrict__ wp,
                                                   const float* __restrict__ x)
{
    const int bid = blockIdx.x;
    if (bid < 288) {
        int idx = bid * 256 + threadIdx.x;          // float2 index; 4*36864/2 total
        if (idx >= 73728) return;
        int mat = idx / 18432, off = idx - mat * 18432;
        const float* src = (mat == 0) ? wq : (mat == 1) ? wk : (mat == 2) ? wv : wp;
        float2 w = ((const float2*)src)[off];
        ((__half2*)g_w)[idx] = __floats2half2_rn(w.x, w.y);
        return;
    }
    __shared__ float sm[32][33];
    const int e = bid - 288;                        // 98*6*2 tiles
    const int p0 = (e % 98) * 32, c0 = ((e / 98) % 6) * 32, b = e / 588;
    const int tx = threadIdx.x & 31, ty = threadIdx.x >> 5;
    #pragma unroll
    for (int j = 0; j < 4; j++)
        sm[ty + 8 * j][tx] = x[((size_t)b * CIN + c0 + ty + 8 * j) * HWSZ + p0 + tx];
    __syncthreads();
    #pragma unroll
    for (int j = 0; j < 4; j++) {
        int p = p0 + ty + 8 * j, c = c0 + tx;
        float v = sm[tx][ty + 8 * j];
        __half h = __float2half_rn(v);
        __half l = __float2half_rn(v - __half2float(h));
        g_xt_hi[((size_t)b * HWSZ + p) * CIN + c] = h;
        g_xt_lo[((size_t)b * HWSZ + p) * CIN + c] = l;
    }
}

// -------- GEMM building blocks (128 threads / 4 warps, 64x64 tile) ----------
#define GTHREADS 128
#define QKV_SMEM  49152   // 2 buffers of 24KB: Ah 8K + Al 8K + B 8K
#define PROJ_SMEM 32768   // 2 buffers of 16KB: A 8K + B 8K

// A chunk (hi+lo) + B chunk -> sbuf: Ah [0,8K), Al [8K,16K), B [16K,24K)
__device__ __forceinline__ void stage_a2b(const __half* __restrict__ Ah, const __half* __restrict__ Al,
                                          const __half* __restrict__ B,
                                          int p0, int c0, uint32_t sbuf)
{
    const int tid = threadIdx.x;
    #pragma unroll
    for (int it = 0; it < 4; it++) {
        int i = tid + it * GTHREADS;            // 512: 64 rows x 8 octs
        int r = i >> 3, oct = i & 7;
        uint32_t db = swz((uint32_t)(r * 128 + oct * 16));
        const size_t aoff = (size_t)(p0 + r) * CIN + c0 + oct * 8;
        const size_t boff = (size_t)r * CIN + c0 + oct * 8;
        cpasync16(sbuf + db,         Ah + aoff);
        cpasync16(sbuf + 8192 + db,  Al + aoff);
        cpasync16(sbuf + 16384 + db, B + boff);
    }
}

// A chunk (hi only) + B chunk -> sbuf: A [0,8K), B [8K,16K)
__device__ __forceinline__ void stage_a1b(const __half* __restrict__ Ah, const __half* __restrict__ B,
                                          int p0, int c0, uint32_t sbuf)
{
    const int tid = threadIdx.x;
    #pragma unroll
    for (int it = 0; it < 4; it++) {
        int i = tid + it * GTHREADS;            // 512: 64 rows x 8 octs
        int r = i >> 3, oct = i & 7;
        uint32_t db = swz((uint32_t)(r * 128 + oct * 16));
        cpasync16(sbuf + db,        Ah + (size_t)(p0 + r) * CIN + c0 + oct * 8);
        cpasync16(sbuf + 8192 + db, B + (size_t)r * CIN + c0 + oct * 8);
    }
}

template<bool TWOPASS>
__device__ __forceinline__ void compute_chunk(uint32_t abuf, uint32_t bbase, float acc[2][4][4])
{
    const int lane = threadIdx.x & 31, wid = threadIdx.x >> 5;
    const int wm = wid & 1, wn = wid >> 1;      // warp tile: rows wm*32, cols wn*32
    const int a_row_l = lane & 15, a_k_l = lane >> 4;
    const int b_row_l = (lane & 7) + ((lane >> 4) << 3), b_k_l = (lane >> 3) & 1;

    #pragma unroll
    for (int ks = 0; ks < 4; ks++) {
        uint32_t ah[2][4], al[2][4], b[2][4];
        #pragma unroll
        for (int np = 0; np < 2; np++) {
            int row = wn * 32 + np * 16 + b_row_l;
            int c16 = ks * 2 + b_k_l;
            ldsm4(b[np], bbase + swz((uint32_t)(row * 128 + c16 * 16)));
        }
        #pragma unroll
        for (int mi = 0; mi < 2; mi++) {
            int row = wm * 32 + mi * 16 + a_row_l;
            int c16 = ks * 2 + a_k_l;
            uint32_t off = swz((uint32_t)(row * 128 + c16 * 16));
            ldsm4(ah[mi], abuf + off);
            if (TWOPASS) ldsm4(al[mi], abuf + 8192 + off);
        }
        #pragma unroll
        for (int mi = 0; mi < 2; mi++)
            #pragma unroll
            for (int ni = 0; ni < 4; ni++) {
                mma16816(acc[mi][ni], ah[mi], &b[ni >> 1][(ni & 1) * 2]);
                if (TWOPASS) mma16816(acc[mi][ni], al[mi], &b[ni >> 1][(ni & 1) * 2]);
            }
    }
}

// QKV: grid (49, 9, 2) = 882 blocks = 1.99 waves at 3 CTAs/SM. 2-pass fp16.
__global__ __launch_bounds__(GTHREADS, 3) void qkv_mma()
{
    extern __shared__ __align__(1024) char smem[];
    const uint32_t sbase = smem_u32(smem);
    const int p0 = blockIdx.x * 64, n0 = blockIdx.y * 64, b = blockIdx.z;
    const __half* Ah = g_xt_hi + (size_t)b * HWSZ * CIN;
    const __half* Al = g_xt_lo + (size_t)b * HWSZ * CIN;
    const __half* B  = g_w + (size_t)n0 * CIN;

    float acc[2][4][4];
    #pragma unroll
    for (int mi = 0; mi < 2; mi++)
        #pragma unroll
        for (int ni = 0; ni < 4; ni++)
            #pragma unroll
            for (int e = 0; e < 4; e++) acc[mi][ni][e] = 0.f;

    stage_a2b(Ah, Al, B, p0, 0, sbase);            CP_COMMIT();
    stage_a2b(Ah, Al, B, p0, 64, sbase + 24576);   CP_COMMIT();

    CP_WAIT(1); __syncthreads();
    compute_chunk<true>(sbase, sbase + 16384, acc);
    __syncthreads();
    stage_a2b(Ah, Al, B, p0, 128, sbase);          CP_COMMIT();
    CP_WAIT(1); __syncthreads();
    compute_chunk<true>(sbase + 24576, sbase + 40960, acc);
    CP_WAIT(0); __syncthreads();
    compute_chunk<true>(sbase, sbase + 16384, acc);

    const int lane = threadIdx.x & 31, wid = threadIdx.x >> 5;
    const int wm = wid & 1, wn = wid >> 1;
    const int gid = lane >> 2, tq = lane & 3;
    float* outb = g_qkv + (size_t)b * HWSZ * 576;
    #pragma unroll
    for (int mi = 0; mi < 2; mi++) {
        const int p = p0 + wm * 32 + mi * 16 + gid;
        #pragma unroll
        for (int ni = 0; ni < 4; ni++) {
            int o = n0 + wn * 32 + ni * 8 + tq * 2;
            *(float2*)&outb[(size_t)p * 576 + o]       = make_float2(acc[mi][ni][0], acc[mi][ni][1]);
            *(float2*)&outb[(size_t)(p + 8) * 576 + o] = make_float2(acc[mi][ni][2], acc[mi][ni][3]);
        }
    }
}

// Projection: grid (49, 3, 2), single-pass fp16 A. Channel-major out via smem.
__global__ __launch_bounds__(GTHREADS, 3) void proj_mma(float* __restrict__ out)
{
    extern __shared__ __align__(1024) char smem[];
    const uint32_t sbase = smem_u32(smem);
    const int p0 = blockIdx.x * 64, n0 = blockIdx.y * 64, b = blockIdx.z;
    const __half* Ah = g_ah + (size_t)b * HWSZ * ODIM;
    const __half* B  = g_w + (size_t)(3 * ODIM + n0) * CIN;

    float acc[2][4][4];
    #pragma unroll
    for (int mi = 0; mi < 2; mi++)
        #pragma unroll
        for (int ni = 0; ni < 4; ni++)
            #pragma unroll
            for (int e = 0; e < 4; e++) acc[mi][ni][e] = 0.f;

    stage_a1b(Ah, B, p0, 0, sbase);            CP_COMMIT();
    stage_a1b(Ah, B, p0, 64, sbase + 16384);   CP_COMMIT();

    CP_WAIT(1); __syncthreads();
    compute_chunk<false>(sbase, sbase + 8192, acc);
    __syncthreads();
    stage_a1b(Ah, B, p0, 128, sbase);          CP_COMMIT();
    CP_WAIT(1); __syncthreads();
    compute_chunk<false>(sbase + 16384, sbase + 24576, acc);
    CP_WAIT(0); __syncthreads();
    compute_chunk<false>(sbase, sbase + 8192, acc);

    const int tid = threadIdx.x, lane = tid & 31, wid = tid >> 5;
    const int wm = wid & 1, wn = wid >> 1;
    const int gid = lane >> 2, tq = lane & 3;
    float* st = (float*)smem;          // [64 o][68 p] = 17408B, reuses buf0
    __syncthreads();
    #pragma unroll
    for (int mi = 0; mi < 2; mi++) {
        const int pl = wm * 32 + mi * 16 + gid;
        #pragma unroll
        for (int ni = 0; ni < 4; ni++) {
            int ol = wn * 32 + ni * 8 + tq * 2;
            st[ol * 68 + pl]           = acc[mi][ni][0];
            st[(ol + 1) * 68 + pl]     = acc[mi][ni][1];
            st[ol * 68 + pl + 8]       = acc[mi][ni][2];
            st[(ol + 1) * 68 + pl + 8] = acc[mi][ni][3];
        }
    }
    __syncthreads();
    float* ob = out + (size_t)b * ODIM * HWSZ;
    #pragma unroll
    for (int it = 0; it < 8; it++) {
        int i = tid + it * GTHREADS;           // 1024: 64 o x 16 quads
        int o = i >> 4, pq = i & 15;
        float4 v = *(const float4*)&st[o * 68 + pq * 4];
        *(float4*)&ob[(size_t)(n0 + o) * HWSZ + p0 + pq * 4] = v;
    }
}

// -------- attention: 8x8 tile, 4 threads/pixel, 4 CTAs/SM -------------------
__global__ __launch_bounds__(256, 4) void attn_kernel(const float* __restrict__ pos)
{
    extern __shared__ __align__(16) float sm2[];
    float* ks = sm2;
    float* vs = sm2 + HPX * 32;
    __shared__ float sbias[13];

    const int tid = threadIdx.x;
    const int x0 = blockIdx.x * TW, y0 = blockIdx.y * TH;
    const int b = blockIdx.z / HEADS, h = blockIdx.z % HEADS;
    if (tid < 13) sbias[tid] = pos[tid];

    const float* base = g_qkv + (size_t)b * HWSZ * 576;
    const int hoff = h * DH;

    for (int idx = tid; idx < HPX * 8; idx += 256) {
        int pix = idx >> 3, g = idx & 7;
        int hy = pix / HLW, hx = pix - hy * HLW;
        int gy = y0 - 3 + hy, gx = x0 - 3 + hx;
        float4 kv = make_float4(0.f, 0.f, 0.f, 0.f);
        float4 vv = make_float4(0.f, 0.f, 0.f, 0.f);
        if (gy >= 0 && gy < IMG && gx >= 0 && gx < IMG) {
            const float* row = base + (size_t)(gy * IMG + gx) * 576 + hoff;
            kv = *(const float4*)(row + 192 + g * 4);
            vv = *(const float4*)(row + 384 + g * 4);
        }
        int slot = g ^ (pix & 7);
        *(float4*)&ks[pix * 32 + slot * 4] = kv;
        *(float4*)&vs[pix * 32 + slot * 4] = vv;
    }
    __syncthreads();

    const int pixel = tid >> 2, qt = tid & 3, lane = tid & 31;
    const int px = pixel & 7, py = pixel >> 3;
    const int gx = x0 + px, gy = y0 + py;
    const float* qrow = base + (size_t)(gy * IMG + gx) * 576 + hoff;

    const int nown = (qt == 0) ? 13 : 12;

    float lg[13];
    #pragma unroll
    for (int j = 0; j < 13; j++) lg[j] = 0.f;
    #pragma unroll
    for (int hf = 0; hf < 4; hf++) {
        float qr[8];
        #pragma unroll
        for (int g = 0; g < 2; g++) {
            float4 q4 = *(const float4*)(qrow + hf * 8 + g * 4);
            qr[4 * g + 0] = q4.x; qr[4 * g + 1] = q4.y; qr[4 * g + 2] = q4.z; qr[4 * g + 3] = q4.w;
        }
        #pragma unroll
        for (int j = 0; j < 13; j++) {
            if (j < nown) {
                const int kk = 4 * j + qt;
                const int di = kk / 7, dj = kk % 7;
                const int hp = (py + di) * HLW + (px + dj);
                const float* kb = &ks[hp * 32];
                const int sw = hp & 7;
                float s0 = 0.f, s1 = 0.f;
                #pragma unroll
                for (int g = 0; g < 2; g++) {
                    const int d4 = hf * 2 + g;
                    float4 kv = *(const float4*)&kb[((d4 ^ sw) << 2)];
                    s0 += kv.x * qr[4 * g + 0] + kv.z * qr[4 * g + 2];
                    s1 += kv.y * qr[4 * g + 1] + kv.w * qr[4 * g + 3];
                }
                lg[j] += s0 + s1;
            }
        }
    }
    #pragma unroll
    for (int j = 0; j < 13; j++) {
        if (j < nown) {
            const int kk = 4 * j + qt;
            lg[j] += sbias[kk / 7 + kk % 7];
        } else lg[j] = -1e30f;
    }

    float mx = -1e30f;
    #pragma unroll
    for (int j = 0; j < 13; j++) mx = fmaxf(mx, lg[j]);
    mx = fmaxf(mx, __shfl_xor_sync(0xffffffffu, mx, 1));
    mx = fmaxf(mx, __shfl_xor_sync(0xffffffffu, mx, 2));
    float sum = 0.f;
    #pragma unroll
    for (int j = 0; j < 13; j++) if (j < nown) { lg[j] = __expf(lg[j] - mx); sum += lg[j]; }
    sum += __shfl_xor_sync(0xffffffffu, sum, 1);
    sum += __shfl_xor_sync(0xffffffffu, sum, 2);
    const float inv = 1.f / sum;
    #pragma unroll
    for (int j = 0; j < 13; j++) lg[j] *= inv;

    float ot[8];
    #pragma unroll
    for (int d = 0; d < 8; d++) ot[d] = 0.f;
    #pragma unroll
    for (int kk = 0; kk < 49; kk++) {
        const int di = kk / 7, dj = kk % 7;
        const int hp = (py + di) * HLW + (px + dj);
        const float* vb = &vs[hp * 32];
        const int sw = hp & 7;
        const float w = __shfl_sync(0xffffffffu, lg[kk >> 2], (lane & 0x1C) | (kk & 3));
        #pragma unroll
        for (int i = 0; i < 2; i++) {
            const int d4 = 2 * qt + i;
            float4 vv = *(const float4*)&vb[((d4 ^ sw) << 2)];
            ot[4 * i + 0] += w * vv.x;
            ot[4 * i + 1] += w * vv.y;
            ot[4 * i + 2] += w * vv.z;
            ot[4 * i + 3] += w * vv.w;
        }
    }

    const size_t orow = ((size_t)b * HWSZ + gy * IMG + gx) * ODIM + hoff + qt * 8;
    __half2* oh = (__half2*)(g_ah + orow);
    #pragma unroll
    for (int j = 0; j < 4; j++)
        oh[j] = __floats2half2_rn(ot[2 * j], ot[2 * j + 1]);
}

// ---------------------------------------------------------------------------
extern "C" void kernel_launch(void* const* d_in, const int* in_sizes, int n_in,
                              void* d_out, int out_size)
{
    const float* x   = (const float*)d_in[0];
    const float* wq  = (const float*)d_in[1];
    const float* wk  = (const float*)d_in[2];
    const float* wv  = (const float*)d_in[3];
    const float* pos = (const float*)d_in[4];
    const float* wp  = (const float*)d_in[5];
    float* out = (float*)d_out;

    const int attn_smem = 2 * HPX * 32 * (int)sizeof(float); // 50176
    cudaFuncSetAttribute(qkv_mma,  cudaFuncAttributeMaxDynamicSharedMemorySize, QKV_SMEM);
    cudaFuncSetAttribute(proj_mma, cudaFuncAttributeMaxDynamicSharedMemorySize, PROJ_SMEM);
    cudaFuncSetAttribute(attn_kernel, cudaFuncAttributeMaxDynamicSharedMemorySize, attn_smem);

    prep_kernel<<<288 + 1176, 256>>>(wq, wk, wv, wp, x);
    qkv_mma<<<dim3(49, 9, 2), GTHREADS, QKV_SMEM>>>();
    attn_kernel<<<dim3(7, 7, 12), 256, attn_smem>>>(pos);
    proj_mma<<<dim3(49, 3, 2), GTHREADS, PROJ_SMEM>>>(out);
}